// round 2
// baseline (speedup 1.0000x reference)
#include <cuda_runtime.h>
#include <math.h>

// ---------------------------------------------------------------------------
// DenoiseGAT on GB300 — fp32 baseline with packed f32x2 FFMA GEMMs.
// Cycle graph => attention is local (prev/next/self), no scatters.
// Round 2 fix: d_in follows setup_inputs() dict order (skips come AFTER all
// per-layer W/asrc/atgt/b blocks), not the reference signature order.
// ---------------------------------------------------------------------------

#define NPOLY  2048
#define VPOLY  64
#define NNODES (NPOLY * VPOLY)   // 131072

// Scratch (device globals — no allocation allowed)
__device__ float g_hA[NNODES * 256];          // 134 MB
__device__ float g_hB[NNODES * 256];          // 134 MB
__device__ float g_proj[NNODES * 512];        // 268 MB
__device__ float g_temb[NPOLY * 128];
__device__ float g_wcat[256 * 512];

// ---------------- packed f32x2 helpers ----------------
__device__ __forceinline__ unsigned long long pk2(float lo, float hi) {
    unsigned long long r;
    asm("mov.b64 %0, {%1, %2};" : "=l"(r) : "r"(__float_as_uint(lo)), "r"(__float_as_uint(hi)));
    return r;
}
__device__ __forceinline__ void fma2(unsigned long long& d, unsigned long long a, unsigned long long b) {
    asm("fma.rn.f32x2 %0, %1, %2, %0;" : "+l"(d) : "l"(a), "l"(b));
}
__device__ __forceinline__ void unpk2(unsigned long long v, float& lo, float& hi) {
    unsigned int l, h;
    asm("mov.b64 {%0, %1}, %2;" : "=r"(l), "=r"(h) : "l"(v));
    lo = __uint_as_float(l); hi = __uint_as_float(h);
}

__device__ __forceinline__ float lrelu02(float x) { return x >= 0.f ? x : 0.2f * x; }
__device__ __forceinline__ float eluf(float x)    { return x > 0.f ? x : (expf(x) - 1.f); }
__device__ __forceinline__ float siluf(float x)   { return x / (1.f + expf(-x)); }

// ---------------------------------------------------------------------------
// GEMM: C[M x Ncols] = A[M x K] * B[K x Ncols]   (+ optional bias & SiLU)
// Block tile 128x128, K-tile 16, 256 threads, 8x8 microtile with f32x2 accs.
// grid = (Ncols/128, M/128)
// ---------------------------------------------------------------------------
template <int ACT>
__global__ __launch_bounds__(256) void gemm_kernel(
    const float* __restrict__ A, int lda, int K,
    const float* __restrict__ B, int ldb,
    float* __restrict__ C, int ldc,
    const float* __restrict__ bias)
{
    __shared__ float As[16][132];   // transposed A tile (pad 4)
    __shared__ float Bs[16][128];

    const int tid  = threadIdx.x;
    const int bm   = blockIdx.y * 128;
    const int bn   = blockIdx.x * 128;
    const int tcol = (tid & 15) * 8;
    const int trow = (tid >> 4) * 8;
    const int ar   = tid >> 2;          // 0..63
    const int ac   = (tid & 3) * 4;     // 0,4,8,12
    const int br   = tid >> 5;          // 0..7
    const int bc   = (tid & 31) * 4;    // 0..124

    unsigned long long acc[8][4];
#pragma unroll
    for (int i = 0; i < 8; i++)
#pragma unroll
        for (int j = 0; j < 4; j++) acc[i][j] = 0ULL;

    const float* Ap0 = A + (size_t)(bm + ar) * lda + ac;
    const float* Ap1 = A + (size_t)(bm + ar + 64) * lda + ac;
    const float* Bp0 = B + (size_t)br * ldb + bn + bc;
    const float* Bp1 = B + (size_t)(br + 8) * ldb + bn + bc;

    for (int k0 = 0; k0 < K; k0 += 16) {
        float4 a0 = *(const float4*)(Ap0 + k0);
        float4 a1 = *(const float4*)(Ap1 + k0);
        float4 b0 = *(const float4*)(Bp0 + (size_t)k0 * ldb);
        float4 b1 = *(const float4*)(Bp1 + (size_t)k0 * ldb);
        As[ac + 0][ar] = a0.x; As[ac + 1][ar] = a0.y; As[ac + 2][ar] = a0.z; As[ac + 3][ar] = a0.w;
        As[ac + 0][ar + 64] = a1.x; As[ac + 1][ar + 64] = a1.y; As[ac + 2][ar + 64] = a1.z; As[ac + 3][ar + 64] = a1.w;
        *(float4*)&Bs[br][bc]     = b0;
        *(float4*)&Bs[br + 8][bc] = b1;
        __syncthreads();
#pragma unroll
        for (int kk = 0; kk < 16; kk++) {
            float4 av0 = *(const float4*)&As[kk][trow];
            float4 av1 = *(const float4*)&As[kk][trow + 4];
            float4 bv0 = *(const float4*)&Bs[kk][tcol];
            float4 bv1 = *(const float4*)&Bs[kk][tcol + 4];
            unsigned long long bp0 = pk2(bv0.x, bv0.y);
            unsigned long long bp1 = pk2(bv0.z, bv0.w);
            unsigned long long bp2 = pk2(bv1.x, bv1.y);
            unsigned long long bp3 = pk2(bv1.z, bv1.w);
            float a[8] = {av0.x, av0.y, av0.z, av0.w, av1.x, av1.y, av1.z, av1.w};
#pragma unroll
            for (int i = 0; i < 8; i++) {
                unsigned long long ap = pk2(a[i], a[i]);
                fma2(acc[i][0], ap, bp0);
                fma2(acc[i][1], ap, bp1);
                fma2(acc[i][2], ap, bp2);
                fma2(acc[i][3], ap, bp3);
            }
        }
        __syncthreads();
    }

#pragma unroll
    for (int i = 0; i < 8; i++) {
        int row = bm + trow + i;
#pragma unroll
        for (int jp = 0; jp < 4; jp++) {
            int col = bn + tcol + jp * 2;
            float lo, hi;
            unpk2(acc[i][jp], lo, hi);
            if (ACT == 1) {
                lo = siluf(lo + bias[col]);
                hi = siluf(hi + bias[col + 1]);
            }
            *(float2*)&C[(size_t)row * ldc + col] = make_float2(lo, hi);
        }
    }
}

// ---------------------------------------------------------------------------
// temb: SinusoidalPosEmb(128) -> Linear(128,128) -> SiLU.  grid=2048, 128 thr
// ---------------------------------------------------------------------------
__global__ void temb_kernel(const int* __restrict__ t, const float* __restrict__ tW,
                            const float* __restrict__ tb, float* __restrict__ temb)
{
    __shared__ float pe[128];
    int b = blockIdx.x, c = threadIdx.x;
    float tv = (float)t[b];
    if (c < 64) {
        float fr = expf(-logf(10000.0f) * (float)c * (1.0f / 63.0f));
        float te = tv * fr;
        pe[c]      = sinf(te);
        pe[c + 64] = cosf(te);
    }
    __syncthreads();
    float acc = tb[c];
#pragma unroll 8
    for (int k = 0; k < 128; k++) acc += pe[k] * tW[k * 128 + c];
    temb[b * 128 + c] = siluf(acc);
}

// ---------------------------------------------------------------------------
// assemble h0 (N x 160, cols 134..159 zero).  grid=N, 160 threads
// ---------------------------------------------------------------------------
__global__ void assemble_kernel(const float* __restrict__ x, const float* __restrict__ temb)
{
    int n = blockIdx.x, c = threadIdx.x;
    int b = n >> 6, v = n & 63;
    float val;
    if (c < 2) {
        val = x[b * 128 + v * 2 + c];
    } else if (c < 6) {
        float ph  = (float)v * (6.283185307179586f / 64.f);
        float arg = (c < 4) ? ph : 2.f * ph;
        val = ((c & 1) == 0) ? sinf(arg) : cosf(arg);
    } else if (c < 134) {
        val = temb[b * 128 + c - 6];
    } else {
        val = 0.f;
    }
    g_hA[(size_t)n * 160 + c] = val;
}

// ---------------------------------------------------------------------------
// Build concatenated weight [W | skip], zero-padded rows to Kpad.
// ---------------------------------------------------------------------------
__global__ void wcat_kernel(const float* __restrict__ W, const float* __restrict__ skip, int K)
{
    int idx = blockIdx.x * blockDim.x + threadIdx.x;
    int k = idx >> 9, n = idx & 511;
    float v = 0.f;
    if (k < K) v = (n < 256) ? W[k * 256 + n] : skip[k * 256 + n - 256];
    g_wcat[idx] = v;
}

// ---------------------------------------------------------------------------
// GAT attention, layers 0-2: NH=4, FOUT=64, concat + skip-proj + bias + ELU.
// One block per polygon. proj layout: N x 512 = [Wproj(256) | skipproj(256)]
// ---------------------------------------------------------------------------
__global__ __launch_bounds__(256) void att4_kernel(
    const float* __restrict__ proj,
    const float* __restrict__ asrc, const float* __restrict__ atgt,
    const float* __restrict__ bias, float* __restrict__ out)
{
    extern __shared__ float sm[];
    float* sp  = sm;            // 64*256
    float* sS  = sm + 16384;    // 256  (j*4+h)
    float* sT  = sS + 256;
    float* aP  = sT + 256;
    float* aN  = aP + 256;
    float* aSf = aN + 256;
    float* sa  = aSf + 256;     // 256
    float* sg  = sa + 256;      // 256

    const int tid = threadIdx.x;
    const int nb  = blockIdx.x * 64;

    for (int i = tid; i < 4096; i += 256) {
        int j = i >> 6, c = (i & 63) << 2;
        *(float4*)&sp[j * 256 + c] = *(const float4*)&proj[(size_t)(nb + j) * 512 + c];
    }
    sa[tid] = asrc[tid];
    sg[tid] = atgt[tid];
    __syncthreads();

    {   // per-(node, head) source/target scores
        int j = tid >> 2, h = tid & 3;
        const float* row = sp + j * 256 + h * 64;
        const float* wa  = sa + h * 64;
        const float* wg  = sg + h * 64;
        float ss = 0.f, st = 0.f;
#pragma unroll 8
        for (int ff = 0; ff < 64; ff++) {
            int f = (ff + tid) & 63;       // rotate to avoid bank conflicts
            float p = row[f];
            ss += p * wa[f];
            st += p * wg[f];
        }
        sS[j * 4 + h] = ss;
        sT[j * 4 + h] = st;
    }
    __syncthreads();

    {   // softmax over {prev, next, self} incoming edges
        int j = tid >> 2, h = tid & 3;
        int jp = (j + 63) & 63, jn = (j + 1) & 63;
        float tg = sT[j * 4 + h];
        float ep = lrelu02(sS[jp * 4 + h] + tg);
        float en = lrelu02(sS[jn * 4 + h] + tg);
        float es = lrelu02(sS[j * 4 + h]  + tg);
        float m  = fmaxf(ep, fmaxf(en, es));
        ep = expf(ep - m); en = expf(en - m); es = expf(es - m);
        float inv = 1.f / (ep + en + es + 1e-16f);
        aP[j * 4 + h]  = ep * inv;
        aN[j * 4 + h]  = en * inv;
        aSf[j * 4 + h] = es * inv;
    }
    __syncthreads();

    {   // aggregate + skip + bias + ELU
        int c = tid, h = tid >> 6;
        float bv = bias[c];
        for (int j = 0; j < 64; j++) {
            int jp = (j + 63) & 63, jn = (j + 1) & 63;
            float v = aP[j * 4 + h]  * sp[jp * 256 + c]
                    + aN[j * 4 + h]  * sp[jn * 256 + c]
                    + aSf[j * 4 + h] * sp[j * 256 + c];
            v += proj[(size_t)(nb + j) * 512 + 256 + c] + bv;
            out[(size_t)(nb + j) * 256 + c] = eluf(v);
        }
    }
}

// ---------------------------------------------------------------------------
// GAT attention, layer 3: NH=1, FOUT=256, identity residual, +bias, no act.
// ---------------------------------------------------------------------------
__global__ __launch_bounds__(256) void att1_kernel(
    const float* __restrict__ proj,      // N x 256
    const float* __restrict__ hprev,     // N x 256
    const float* __restrict__ asrc, const float* __restrict__ atgt,
    const float* __restrict__ bias, float* __restrict__ out)
{
    extern __shared__ float sm[];
    float* sp   = sm;             // 64*256
    float* redS = sm + 16384;     // 256
    float* redT = redS + 256;     // 256
    float* sS   = redT + 256;     // 64
    float* sT   = sS + 64;
    float* aP   = sT + 64;
    float* aN   = aP + 64;
    float* aSf  = aN + 64;
    float* sa   = aSf + 64;       // 256
    float* sg   = sa + 256;       // 256

    const int tid = threadIdx.x;
    const int nb  = blockIdx.x * 64;

    for (int i = tid; i < 4096; i += 256) {
        int j = i >> 6, c = (i & 63) << 2;
        *(float4*)&sp[j * 256 + c] = *(const float4*)&proj[(size_t)(nb + j) * 256 + c];
    }
    sa[tid] = asrc[tid];
    sg[tid] = atgt[tid];
    __syncthreads();

    {   // partial dots over 256 features (4 partials of 64 per node)
        int j = tid & 63, r = tid >> 6;
        float ss = 0.f, st = 0.f;
#pragma unroll 8
        for (int ff = 0; ff < 64; ff++) {
            int f = r * 64 + ((ff + tid) & 63);
            float p = sp[j * 256 + f];
            ss += p * sa[f];
            st += p * sg[f];
        }
        redS[tid] = ss;
        redT[tid] = st;
    }
    __syncthreads();
    if (tid < 64) {
        sS[tid] = redS[tid] + redS[tid + 64] + redS[tid + 128] + redS[tid + 192];
        sT[tid] = redT[tid] + redT[tid + 64] + redT[tid + 128] + redT[tid + 192];
    }
    __syncthreads();
    if (tid < 64) {
        int j = tid, jp = (j + 63) & 63, jn = (j + 1) & 63;
        float tg = sT[j];
        float ep = lrelu02(sS[jp] + tg);
        float en = lrelu02(sS[jn] + tg);
        float es = lrelu02(sS[j]  + tg);
        float m  = fmaxf(ep, fmaxf(en, es));
        ep = expf(ep - m); en = expf(en - m); es = expf(es - m);
        float inv = 1.f / (ep + en + es + 1e-16f);
        aP[j] = ep * inv; aN[j] = en * inv; aSf[j] = es * inv;
    }
    __syncthreads();

    {
        int c = tid;
        float bv = bias[c];
        for (int j = 0; j < 64; j++) {
            int jp = (j + 63) & 63, jn = (j + 1) & 63;
            float v = aP[j] * sp[jp * 256 + c]
                    + aN[j] * sp[jn * 256 + c]
                    + aSf[j] * sp[j * 256 + c];
            v += hprev[(size_t)(nb + j) * 256 + c] + bv;
            out[(size_t)(nb + j) * 256 + c] = v;
        }
    }
}

// ---------------------------------------------------------------------------
// Final projection: out[n, 0:2] = h[n, :] @ h2W + h2b. One warp per node.
// ---------------------------------------------------------------------------
__global__ __launch_bounds__(256) void out_kernel(
    const float* __restrict__ h, const float* __restrict__ w,
    const float* __restrict__ b2, float* __restrict__ out)
{
    int gw   = blockIdx.x * 8 + (threadIdx.x >> 5);
    int lane = threadIdx.x & 31;
    const float* hr = h + (size_t)gw * 256;
    float s0 = 0.f, s1 = 0.f;
#pragma unroll
    for (int k = lane; k < 256; k += 32) {
        float hv = hr[k];
        s0 += hv * w[k * 2];
        s1 += hv * w[k * 2 + 1];
    }
#pragma unroll
    for (int off = 16; off; off >>= 1) {
        s0 += __shfl_down_sync(0xffffffffu, s0, off);
        s1 += __shfl_down_sync(0xffffffffu, s1, off);
    }
    if (lane == 0) {
        out[(size_t)gw * 2]     = s0 + b2[0];
        out[(size_t)gw * 2 + 1] = s1 + b2[1];
    }
}

// ---------------------------------------------------------------------------
extern "C" void kernel_launch(void* const* d_in, const int* in_sizes, int n_in,
                              void* d_out, int out_size)
{
    // setup_inputs() dict order:
    //  0:x 1:t 2:tW 3:tb
    //  4:W0 5:asrc0 6:atgt0 7:b0
    //  8:W1 9:asrc1 10:atgt1 11:b1
    //  12:W2 13:asrc2 14:atgt2 15:b2
    //  16:W3 17:asrc3 18:atgt3 19:b3
    //  20:skip0 21:skip1 22:skip2
    //  23:h1W 24:h1b 25:h2W 26:h2b
    const float* x   = (const float*)d_in[0];
    const int*   t   = (const int*)  d_in[1];
    const float* tW  = (const float*)d_in[2];
    const float* tb  = (const float*)d_in[3];
    const float* W0  = (const float*)d_in[4];
    const float* as0 = (const float*)d_in[5];
    const float* at0 = (const float*)d_in[6];
    const float* b0  = (const float*)d_in[7];
    const float* W1  = (const float*)d_in[8];
    const float* as1 = (const float*)d_in[9];
    const float* at1 = (const float*)d_in[10];
    const float* b1  = (const float*)d_in[11];
    const float* W2  = (const float*)d_in[12];
    const float* as2 = (const float*)d_in[13];
    const float* at2 = (const float*)d_in[14];
    const float* b2_ = (const float*)d_in[15];
    const float* W3  = (const float*)d_in[16];
    const float* as3 = (const float*)d_in[17];
    const float* at3 = (const float*)d_in[18];
    const float* b3  = (const float*)d_in[19];
    const float* sk0 = (const float*)d_in[20];
    const float* sk1 = (const float*)d_in[21];
    const float* sk2 = (const float*)d_in[22];
    const float* h1W = (const float*)d_in[23];
    const float* h1b = (const float*)d_in[24];
    const float* h2W = (const float*)d_in[25];
    const float* h2b = (const float*)d_in[26];
    float* out = (float*)d_out;

    float *hA, *hB, *proj, *temb, *wcat;
    cudaGetSymbolAddress((void**)&hA,   g_hA);
    cudaGetSymbolAddress((void**)&hB,   g_hB);
    cudaGetSymbolAddress((void**)&proj, g_proj);
    cudaGetSymbolAddress((void**)&temb, g_temb);
    cudaGetSymbolAddress((void**)&wcat, g_wcat);

    cudaFuncSetAttribute(att4_kernel, cudaFuncAttributeMaxDynamicSharedMemorySize, 73728);
    cudaFuncSetAttribute(att1_kernel, cudaFuncAttributeMaxDynamicSharedMemorySize, 73728);

    const int ATT4_SMEM = (16384 + 7 * 256) * 4;
    const int ATT1_SMEM = (16384 + 2 * 256 + 6 * 64 + 2 * 256) * 4;

    // time embedding + node features
    temb_kernel<<<NPOLY, 128>>>(t, tW, tb, temb);
    assemble_kernel<<<NNODES, 160>>>(x, temb);

    // layer 0: K=134 padded to 160
    wcat_kernel<<<(160 * 512) / 256, 256>>>(W0, sk0, 134);
    gemm_kernel<0><<<dim3(4, NNODES / 128), 256>>>(hA, 160, 160, wcat, 512, proj, 512, nullptr);
    att4_kernel<<<NPOLY, 256, ATT4_SMEM>>>(proj, as0, at0, b0, hB);

    // layer 1
    wcat_kernel<<<(256 * 512) / 256, 256>>>(W1, sk1, 256);
    gemm_kernel<0><<<dim3(4, NNODES / 128), 256>>>(hB, 256, 256, wcat, 512, proj, 512, nullptr);
    att4_kernel<<<NPOLY, 256, ATT4_SMEM>>>(proj, as1, at1, b1, hA);

    // layer 2
    wcat_kernel<<<(256 * 512) / 256, 256>>>(W2, sk2, 256);
    gemm_kernel<0><<<dim3(4, NNODES / 128), 256>>>(hA, 256, 256, wcat, 512, proj, 512, nullptr);
    att4_kernel<<<NPOLY, 256, ATT4_SMEM>>>(proj, as2, at2, b2_, hB);

    // layer 3 (NH=1, identity residual, no act)
    gemm_kernel<0><<<dim3(2, NNODES / 128), 256>>>(hB, 256, 256, W3, 256, proj, 256, nullptr);
    att1_kernel<<<NPOLY, 256, ATT1_SMEM>>>(proj, hB, as3, at3, b3, hA);

    // head: silu(h @ h1W + h1b), then h @ h2W + h2b
    gemm_kernel<1><<<dim3(2, NNODES / 128), 256>>>(hA, 256, 256, h1W, 256, hB, 256, h1b);
    out_kernel<<<NNODES / 8, 256>>>(hB, h2W, h2b, out);
}

// round 4
// speedup vs baseline: 1.9634x; 1.9634x over previous
#include <cuda_runtime.h>
#include <cuda_bf16.h>
#include <cstdint>
#include <math.h>

// ---------------------------------------------------------------------------
// DenoiseGAT on GB300 — Round 4: GEMMs on mma.sync bf16 (HMMA) with 3-term
// bf16 split + cp.async double buffering. (tcgen05 unavailable: harness PTX
// target is compute_103, arch-'a' instructions rejected by ptxas.)
// ---------------------------------------------------------------------------

#define NPOLY  2048
#define VPOLY  64
#define NNODES (NPOLY * VPOLY)   // 131072

// Scratch (device globals — no allocation allowed)
__device__ __align__(128) __nv_bfloat16 g_hhi[NNODES * 256];
__device__ __align__(128) __nv_bfloat16 g_hlo[NNODES * 256];
__device__ __align__(128) float          g_h32[NNODES * 256];
__device__ __align__(128) float          g_proj[NNODES * 512];
__device__ __align__(128) float          g_temb[NPOLY * 128];
__device__ __align__(128) __nv_bfloat16 g_whi[512 * 256];
__device__ __align__(128) __nv_bfloat16 g_wlo[512 * 256];

__device__ __forceinline__ uint32_t smem_u32(const void* p) {
    uint32_t a;
    asm("{ .reg .u64 t; cvta.to.shared.u64 t, %1; cvt.u32.u64 %0, t; }" : "=r"(a) : "l"(p));
    return a;
}
__device__ __forceinline__ void cp16(uint32_t dst, const void* src) {
    asm volatile("cp.async.cg.shared.global [%0], [%1], 16;" :: "r"(dst), "l"(src) : "memory");
}
#define CP_COMMIT() asm volatile("cp.async.commit_group;" ::: "memory")
#define CP_WAIT0()  asm volatile("cp.async.wait_group 0;" ::: "memory")
#define CP_WAIT1()  asm volatile("cp.async.wait_group 1;" ::: "memory")

__device__ __forceinline__ void ldmx4(uint32_t& r0, uint32_t& r1, uint32_t& r2, uint32_t& r3, uint32_t addr) {
    asm volatile("ldmatrix.sync.aligned.m8n8.x4.shared.b16 {%0,%1,%2,%3}, [%4];"
                 : "=r"(r0), "=r"(r1), "=r"(r2), "=r"(r3) : "r"(addr));
}
__device__ __forceinline__ void mma_bf16(float* d, const uint32_t* a, const uint32_t* b) {
    asm volatile(
        "mma.sync.aligned.m16n8k16.row.col.f32.bf16.bf16.f32 "
        "{%0,%1,%2,%3}, {%4,%5,%6,%7}, {%8,%9}, {%0,%1,%2,%3};"
        : "+f"(d[0]), "+f"(d[1]), "+f"(d[2]), "+f"(d[3])
        : "r"(a[0]), "r"(a[1]), "r"(a[2]), "r"(a[3]), "r"(b[0]), "r"(b[1]));
}

__device__ __forceinline__ float lrelu02(float x) { return x >= 0.f ? x : 0.2f * x; }
__device__ __forceinline__ float eluf(float x)    { return x > 0.f ? x : (expf(x) - 1.f); }
__device__ __forceinline__ float siluf(float x)   { return x / (1.f + expf(-x)); }
__device__ __forceinline__ void split_bf16(float v, __nv_bfloat16& h, __nv_bfloat16& l) {
    h = __float2bfloat16(v);
    l = __float2bfloat16(v - __bfloat162float(h));
}

// ---------------------------------------------------------------------------
// HMMA GEMM: C[M x N] = A[M x K] * Bt[N x K]^T  (3-term bf16 split, fp32 acc)
// CTA 128x128, K-tile 32, 256 thr (8 warps: 2m x 4n, warp tile 64x32),
// cp.async 2-stage. grid=(N/128, M/128). Smem row stride 80B (conflict-free).
// ---------------------------------------------------------------------------
#define TILE_B   10240            // one operand tile: 128 rows * 80B
#define STAGE_B  (4 * TILE_B)     // Ahi, Alo, Bhi, Blo

template <int ACT>
__global__ __launch_bounds__(256) void gemm_tc(
    const __nv_bfloat16* __restrict__ Ahi, const __nv_bfloat16* __restrict__ Alo,
    const __nv_bfloat16* __restrict__ Bhi, const __nv_bfloat16* __restrict__ Blo,
    int K, float* __restrict__ C, int ldc, const float* __restrict__ bias)
{
    extern __shared__ char smem[];
    const uint32_t sb = smem_u32(smem);

    const int tid  = threadIdx.x;
    const int lane = tid & 31;
    const int wid  = tid >> 5;
    const int wm   = wid & 1;          // 0..1  (64 rows each)
    const int wn   = wid >> 1;         // 0..3  (32 cols each)
    const int bm   = blockIdx.y * 128;
    const int bn   = blockIdx.x * 128;
    const int KT   = K >> 5;

    // cp.async mapping: idx = tid + p*256 -> row = idx>>2, chunk = idx&3
    const int r0c = (tid) >> 2,        c0 = (tid & 3);
    const int r1c = (tid + 256) >> 2,  c1 = (tid & 3);   // (tid+256)&3 == tid&3

    float acc[4][4][4];
#pragma unroll
    for (int i = 0; i < 4; i++)
#pragma unroll
        for (int j = 0; j < 4; j++)
#pragma unroll
            for (int k = 0; k < 4; k++) acc[i][j][k] = 0.f;

#define ISSUE_STAGE(kt, s)                                                            \
    do {                                                                              \
        int kof = (kt) * 32;                                                          \
        uint32_t sba = sb + (s) * STAGE_B;                                            \
        cp16(sba + r0c * 80 + c0 * 16,              Ahi + (size_t)(bm + r0c) * K + kof + c0 * 8); \
        cp16(sba + r1c * 80 + c1 * 16,              Ahi + (size_t)(bm + r1c) * K + kof + c1 * 8); \
        cp16(sba + TILE_B + r0c * 80 + c0 * 16,     Alo + (size_t)(bm + r0c) * K + kof + c0 * 8); \
        cp16(sba + TILE_B + r1c * 80 + c1 * 16,     Alo + (size_t)(bm + r1c) * K + kof + c1 * 8); \
        cp16(sba + 2 * TILE_B + r0c * 80 + c0 * 16, Bhi + (size_t)(bn + r0c) * K + kof + c0 * 8); \
        cp16(sba + 2 * TILE_B + r1c * 80 + c1 * 16, Bhi + (size_t)(bn + r1c) * K + kof + c1 * 8); \
        cp16(sba + 3 * TILE_B + r0c * 80 + c0 * 16, Blo + (size_t)(bn + r0c) * K + kof + c0 * 8); \
        cp16(sba + 3 * TILE_B + r1c * 80 + c1 * 16, Blo + (size_t)(bn + r1c) * K + kof + c1 * 8); \
    } while (0)

    ISSUE_STAGE(0, 0);
    CP_COMMIT();

    // ldmatrix per-lane bases
    const int aRow  = wm * 64 + (lane & 15);     // + mf*16
    const int aHalf = lane >> 4;                 // chunk half
    const int bRow  = wn * 32 + (lane & 7) + ((lane >> 4) << 3);  // + nfp*16
    const int bHalf = (lane >> 3) & 1;

    for (int kt = 0; kt < KT; kt++) {
        if (kt + 1 < KT) {
            ISSUE_STAGE(kt + 1, (kt + 1) & 1);
            CP_COMMIT();
            CP_WAIT1();
        } else {
            CP_WAIT0();
        }
        __syncthreads();

        const uint32_t sba = sb + (kt & 1) * STAGE_B;
#pragma unroll
        for (int ks = 0; ks < 2; ks++) {
            uint32_t Ah[4][4], Al[4][4], Bh[4][2], Bl[4][2];
#pragma unroll
            for (int mf = 0; mf < 4; mf++) {
                uint32_t ad = sba + (aRow + mf * 16) * 80 + (2 * ks + aHalf) * 16;
                ldmx4(Ah[mf][0], Ah[mf][1], Ah[mf][2], Ah[mf][3], ad);
                ldmx4(Al[mf][0], Al[mf][1], Al[mf][2], Al[mf][3], ad + TILE_B);
            }
#pragma unroll
            for (int nfp = 0; nfp < 2; nfp++) {
                uint32_t bd = sba + 2 * TILE_B + (bRow + nfp * 16) * 80 + (2 * ks + bHalf) * 16;
                uint32_t q0, q1, q2, q3;
                ldmx4(q0, q1, q2, q3, bd);
                Bh[nfp * 2][0] = q0; Bh[nfp * 2][1] = q1;
                Bh[nfp * 2 + 1][0] = q2; Bh[nfp * 2 + 1][1] = q3;
                ldmx4(q0, q1, q2, q3, bd + TILE_B);
                Bl[nfp * 2][0] = q0; Bl[nfp * 2][1] = q1;
                Bl[nfp * 2 + 1][0] = q2; Bl[nfp * 2 + 1][1] = q3;
            }
#pragma unroll
            for (int mf = 0; mf < 4; mf++)
#pragma unroll
                for (int nf = 0; nf < 4; nf++) {
                    mma_bf16(acc[mf][nf], Ah[mf], Bh[nf]);
                    mma_bf16(acc[mf][nf], Ah[mf], Bl[nf]);
                    mma_bf16(acc[mf][nf], Al[mf], Bh[nf]);
                }
        }
        __syncthreads();
    }

    // epilogue
#pragma unroll
    for (int mf = 0; mf < 4; mf++) {
        int m0 = bm + wm * 64 + mf * 16 + (lane >> 2);
#pragma unroll
        for (int nf = 0; nf < 4; nf++) {
            int n0 = bn + wn * 32 + nf * 8 + (lane & 3) * 2;
            float v0 = acc[mf][nf][0], v1 = acc[mf][nf][1];
            float v2 = acc[mf][nf][2], v3 = acc[mf][nf][3];
            if (ACT == 1) {
                float bb0 = bias[n0], bb1 = bias[n0 + 1];
                v0 = siluf(v0 + bb0); v1 = siluf(v1 + bb1);
                v2 = siluf(v2 + bb0); v3 = siluf(v3 + bb1);
            }
            *(float2*)&C[(size_t)m0 * ldc + n0]       = make_float2(v0, v1);
            *(float2*)&C[(size_t)(m0 + 8) * ldc + n0] = make_float2(v2, v3);
        }
    }
}

// ---------------------------------------------------------------------------
// temb: SinusoidalPosEmb(128) -> Linear(128,128) -> SiLU.  grid=2048, 128 thr
// ---------------------------------------------------------------------------
__global__ void temb_kernel(const int* __restrict__ t, const float* __restrict__ tW,
                            const float* __restrict__ tb, float* __restrict__ temb)
{
    __shared__ float pe[128];
    int b = blockIdx.x, c = threadIdx.x;
    float tv = (float)t[b];
    if (c < 64) {
        float fr = expf(-logf(10000.0f) * (float)c * (1.0f / 63.0f));
        float te = tv * fr;
        pe[c]      = sinf(te);
        pe[c + 64] = cosf(te);
    }
    __syncthreads();
    float acc = tb[c];
#pragma unroll 8
    for (int k = 0; k < 128; k++) acc += pe[k] * tW[k * 128 + c];
    temb[b * 128 + c] = siluf(acc);
}

// ---------------------------------------------------------------------------
// assemble h0 (N x 160 bf16 hi/lo, cols 134..159 zero).  grid=N, 160 threads
// ---------------------------------------------------------------------------
__global__ void assemble_kernel(const float* __restrict__ x, const float* __restrict__ temb)
{
    int n = blockIdx.x, c = threadIdx.x;
    int b = n >> 6, v = n & 63;
    float val = 0.f;
    if (c < 2) {
        val = x[b * 128 + v * 2 + c];
    } else if (c < 6) {
        float ph  = (float)v * (6.283185307179586f / 64.f);
        float arg = (c < 4) ? ph : 2.f * ph;
        val = ((c & 1) == 0) ? sinf(arg) : cosf(arg);
    } else if (c < 134) {
        val = temb[b * 128 + c - 6];
    }
    __nv_bfloat16 h, l;
    split_bf16(val, h, l);
    g_hhi[(size_t)n * 160 + c] = h;
    g_hlo[(size_t)n * 160 + c] = l;
}

// ---------------------------------------------------------------------------
// Weight prep: Bt[n][k] transposed + bf16 split.
// ---------------------------------------------------------------------------
__global__ void wprep_cat(const float* __restrict__ W, const float* __restrict__ skip,
                          int K, int Kpad)
{
    int idx = blockIdx.x * 256 + threadIdx.x;
    if (idx >= 512 * Kpad) return;
    int n = idx / Kpad, k = idx % Kpad;
    float v = 0.f;
    if (k < K) v = (n < 256) ? W[k * 256 + n] : skip[k * 256 + (n - 256)];
    __nv_bfloat16 h, l;
    split_bf16(v, h, l);
    g_whi[idx] = h; g_wlo[idx] = l;
}
__global__ void wprep_t(const float* __restrict__ W)   // 256x256 transpose
{
    int idx = blockIdx.x * 256 + threadIdx.x;
    int n = idx >> 8, k = idx & 255;
    float v = W[k * 256 + n];
    __nv_bfloat16 h, l;
    split_bf16(v, h, l);
    g_whi[idx] = h; g_wlo[idx] = l;
}

// ---------------------------------------------------------------------------
// GAT attention, layers 0-2: NH=4, FOUT=64, concat + skip-proj + bias + ELU.
// Writes bf16 hi/lo (+ fp32 if WRITE32). One block per polygon.
// ---------------------------------------------------------------------------
template <int WRITE32>
__global__ __launch_bounds__(256) void att4_kernel(
    const float* __restrict__ proj,
    const float* __restrict__ asrc, const float* __restrict__ atgt,
    const float* __restrict__ bias)
{
    extern __shared__ float sm[];
    float* sp  = sm;            // 64*256
    float* sS  = sm + 16384;    // 256  (j*4+h)
    float* sT  = sS + 256;
    float* aP  = sT + 256;
    float* aN  = aP + 256;
    float* aSf = aN + 256;
    float* sa  = aSf + 256;     // 256
    float* sg  = sa + 256;      // 256

    const int tid = threadIdx.x;
    const int nb  = blockIdx.x * 64;

    for (int i = tid; i < 4096; i += 256) {
        int j = i >> 6, c = (i & 63) << 2;
        *(float4*)&sp[j * 256 + c] = *(const float4*)&proj[(size_t)(nb + j) * 512 + c];
    }
    sa[tid] = asrc[tid];
    sg[tid] = atgt[tid];
    __syncthreads();

    {
        int j = tid >> 2, h = tid & 3;
        const float* row = sp + j * 256 + h * 64;
        const float* wa  = sa + h * 64;
        const float* wg  = sg + h * 64;
        float ss = 0.f, st = 0.f;
#pragma unroll 8
        for (int ff = 0; ff < 64; ff++) {
            int f = (ff + tid) & 63;
            float p = row[f];
            ss += p * wa[f];
            st += p * wg[f];
        }
        sS[j * 4 + h] = ss;
        sT[j * 4 + h] = st;
    }
    __syncthreads();

    {
        int j = tid >> 2, h = tid & 3;
        int jp = (j + 63) & 63, jn = (j + 1) & 63;
        float tg = sT[j * 4 + h];
        float ep = lrelu02(sS[jp * 4 + h] + tg);
        float en = lrelu02(sS[jn * 4 + h] + tg);
        float es = lrelu02(sS[j * 4 + h]  + tg);
        float m  = fmaxf(ep, fmaxf(en, es));
        ep = expf(ep - m); en = expf(en - m); es = expf(es - m);
        float inv = 1.f / (ep + en + es + 1e-16f);
        aP[j * 4 + h]  = ep * inv;
        aN[j * 4 + h]  = en * inv;
        aSf[j * 4 + h] = es * inv;
    }
    __syncthreads();

    {
        int c = tid, h = tid >> 6;
        float bv = bias[c];
        for (int j = 0; j < 64; j++) {
            int jp = (j + 63) & 63, jn = (j + 1) & 63;
            float v = aP[j * 4 + h]  * sp[jp * 256 + c]
                    + aN[j * 4 + h]  * sp[jn * 256 + c]
                    + aSf[j * 4 + h] * sp[j * 256 + c];
            v += proj[(size_t)(nb + j) * 512 + 256 + c] + bv;
            v = eluf(v);
            size_t o = (size_t)(nb + j) * 256 + c;
            __nv_bfloat16 hh, ll;
            split_bf16(v, hh, ll);
            g_hhi[o] = hh; g_hlo[o] = ll;
            if (WRITE32) g_h32[o] = v;
        }
    }
}

// ---------------------------------------------------------------------------
// GAT attention, layer 3: NH=1, FOUT=256, identity residual, +bias, no act.
// ---------------------------------------------------------------------------
__global__ __launch_bounds__(256) void att1_kernel(
    const float* __restrict__ proj,      // N x 256
    const float* __restrict__ hprev,     // N x 256 (fp32)
    const float* __restrict__ asrc, const float* __restrict__ atgt,
    const float* __restrict__ bias)
{
    extern __shared__ float sm[];
    float* sp   = sm;             // 64*256
    float* redS = sm + 16384;     // 256
    float* redT = redS + 256;
    float* sS   = redT + 256;     // 64
    float* sT   = sS + 64;
    float* aP   = sT + 64;
    float* aN   = aP + 64;
    float* aSf  = aN + 64;
    float* sa   = aSf + 64;       // 256
    float* sg   = sa + 256;

    const int tid = threadIdx.x;
    const int nb  = blockIdx.x * 64;

    for (int i = tid; i < 4096; i += 256) {
        int j = i >> 6, c = (i & 63) << 2;
        *(float4*)&sp[j * 256 + c] = *(const float4*)&proj[(size_t)(nb + j) * 256 + c];
    }
    sa[tid] = asrc[tid];
    sg[tid] = atgt[tid];
    __syncthreads();

    {
        int j = tid & 63, r = tid >> 6;
        float ss = 0.f, st = 0.f;
#pragma unroll 8
        for (int ff = 0; ff < 64; ff++) {
            int f = r * 64 + ((ff + tid) & 63);
            float p = sp[j * 256 + f];
            ss += p * sa[f];
            st += p * sg[f];
        }
        redS[tid] = ss;
        redT[tid] = st;
    }
    __syncthreads();
    if (tid < 64) {
        sS[tid] = redS[tid] + redS[tid + 64] + redS[tid + 128] + redS[tid + 192];
        sT[tid] = redT[tid] + redT[tid + 64] + redT[tid + 128] + redT[tid + 192];
    }
    __syncthreads();
    if (tid < 64) {
        int j = tid, jp = (j + 63) & 63, jn = (j + 1) & 63;
        float tg = sT[j];
        float ep = lrelu02(sS[jp] + tg);
        float en = lrelu02(sS[jn] + tg);
        float es = lrelu02(sS[j]  + tg);
        float m  = fmaxf(ep, fmaxf(en, es));
        ep = expf(ep - m); en = expf(en - m); es = expf(es - m);
        float inv = 1.f / (ep + en + es + 1e-16f);
        aP[j] = ep * inv; aN[j] = en * inv; aSf[j] = es * inv;
    }
    __syncthreads();

    {
        int c = tid;
        float bv = bias[c];
        for (int j = 0; j < 64; j++) {
            int jp = (j + 63) & 63, jn = (j + 1) & 63;
            float v = aP[j] * sp[jp * 256 + c]
                    + aN[j] * sp[jn * 256 + c]
                    + aSf[j] * sp[j * 256 + c];
            v += hprev[(size_t)(nb + j) * 256 + c] + bv;
            size_t o = (size_t)(nb + j) * 256 + c;
            __nv_bfloat16 hh, ll;
            split_bf16(v, hh, ll);
            g_hhi[o] = hh; g_hlo[o] = ll;
        }
    }
}

// ---------------------------------------------------------------------------
// Final projection: out[n, 0:2] = h[n, :] @ h2W + h2b. One warp per node.
// ---------------------------------------------------------------------------
__global__ __launch_bounds__(256) void out_kernel(
    const float* __restrict__ h, const float* __restrict__ w,
    const float* __restrict__ b2, float* __restrict__ out)
{
    int gw   = blockIdx.x * 8 + (threadIdx.x >> 5);
    int lane = threadIdx.x & 31;
    const float* hr = h + (size_t)gw * 256;
    float s0 = 0.f, s1 = 0.f;
#pragma unroll
    for (int k = lane; k < 256; k += 32) {
        float hv = hr[k];
        s0 += hv * w[k * 2];
        s1 += hv * w[k * 2 + 1];
    }
#pragma unroll
    for (int off = 16; off; off >>= 1) {
        s0 += __shfl_down_sync(0xffffffffu, s0, off);
        s1 += __shfl_down_sync(0xffffffffu, s1, off);
    }
    if (lane == 0) {
        out[(size_t)gw * 2]     = s0 + b2[0];
        out[(size_t)gw * 2 + 1] = s1 + b2[1];
    }
}

// ---------------------------------------------------------------------------
extern "C" void kernel_launch(void* const* d_in, const int* in_sizes, int n_in,
                              void* d_out, int out_size)
{
    // setup_inputs() dict order
    const float* x   = (const float*)d_in[0];
    const int*   t   = (const int*)  d_in[1];
    const float* tW  = (const float*)d_in[2];
    const float* tb  = (const float*)d_in[3];
    const float* W0  = (const float*)d_in[4];
    const float* as0 = (const float*)d_in[5];
    const float* at0 = (const float*)d_in[6];
    const float* b0  = (const float*)d_in[7];
    const float* W1  = (const float*)d_in[8];
    const float* as1 = (const float*)d_in[9];
    const float* at1 = (const float*)d_in[10];
    const float* b1  = (const float*)d_in[11];
    const float* W2  = (const float*)d_in[12];
    const float* as2 = (const float*)d_in[13];
    const float* at2 = (const float*)d_in[14];
    const float* b2_ = (const float*)d_in[15];
    const float* W3  = (const float*)d_in[16];
    const float* as3 = (const float*)d_in[17];
    const float* at3 = (const float*)d_in[18];
    const float* b3  = (const float*)d_in[19];
    const float* sk0 = (const float*)d_in[20];
    const float* sk1 = (const float*)d_in[21];
    const float* sk2 = (const float*)d_in[22];
    const float* h1W = (const float*)d_in[23];
    const float* h1b = (const float*)d_in[24];
    const float* h2W = (const float*)d_in[25];
    const float* h2b = (const float*)d_in[26];
    float* out = (float*)d_out;

    __nv_bfloat16 *hhi, *hlo, *whi, *wlo;
    float *h32, *proj, *temb;
    cudaGetSymbolAddress((void**)&hhi,  g_hhi);
    cudaGetSymbolAddress((void**)&hlo,  g_hlo);
    cudaGetSymbolAddress((void**)&h32,  g_h32);
    cudaGetSymbolAddress((void**)&proj, g_proj);
    cudaGetSymbolAddress((void**)&temb, g_temb);
    cudaGetSymbolAddress((void**)&whi,  g_whi);
    cudaGetSymbolAddress((void**)&wlo,  g_wlo);

    const int GEMM_SMEM = 2 * STAGE_B;   // 81920
    cudaFuncSetAttribute(gemm_tc<0>, cudaFuncAttributeMaxDynamicSharedMemorySize, GEMM_SMEM);
    cudaFuncSetAttribute(gemm_tc<1>, cudaFuncAttributeMaxDynamicSharedMemorySize, GEMM_SMEM);
    cudaFuncSetAttribute(att4_kernel<0>, cudaFuncAttributeMaxDynamicSharedMemorySize, 73728);
    cudaFuncSetAttribute(att4_kernel<1>, cudaFuncAttributeMaxDynamicSharedMemorySize, 73728);
    cudaFuncSetAttribute(att1_kernel,    cudaFuncAttributeMaxDynamicSharedMemorySize, 73728);

    const int ATT4_SMEM = (16384 + 7 * 256) * 4;
    const int ATT1_SMEM = (16384 + 2 * 256 + 6 * 64 + 2 * 256) * 4;
    const dim3 G512(4, NNODES / 128), G256(2, NNODES / 128);

    // time embedding + node features (bf16 split, Kpad=160)
    temb_kernel<<<NPOLY, 128>>>(t, tW, tb, temb);
    assemble_kernel<<<NNODES, 160>>>(x, temb);

    // layer 0: K=134 padded to 160
    wprep_cat<<<(512 * 160 + 255) / 256, 256>>>(W0, sk0, 134, 160);
    gemm_tc<0><<<G512, 256, GEMM_SMEM>>>(hhi, hlo, whi, wlo, 160, proj, 512, nullptr);
    att4_kernel<0><<<NPOLY, 256, ATT4_SMEM>>>(proj, as0, at0, b0);

    // layer 1
    wprep_cat<<<(512 * 256 + 255) / 256, 256>>>(W1, sk1, 256, 256);
    gemm_tc<0><<<G512, 256, GEMM_SMEM>>>(hhi, hlo, whi, wlo, 256, proj, 512, nullptr);
    att4_kernel<0><<<NPOLY, 256, ATT4_SMEM>>>(proj, as1, at1, b1);

    // layer 2 (fp32 output needed for layer-3 residual)
    wprep_cat<<<(512 * 256 + 255) / 256, 256>>>(W2, sk2, 256, 256);
    gemm_tc<0><<<G512, 256, GEMM_SMEM>>>(hhi, hlo, whi, wlo, 256, proj, 512, nullptr);
    att4_kernel<1><<<NPOLY, 256, ATT4_SMEM>>>(proj, as2, at2, b2_);

    // layer 3 (NH=1, identity residual, no act)
    wprep_t<<<(256 * 256) / 256, 256>>>(W3);
    gemm_tc<0><<<G256, 256, GEMM_SMEM>>>(hhi, hlo, whi, wlo, 256, proj, 256, nullptr);
    att1_kernel<<<NPOLY, 256, ATT1_SMEM>>>(proj, h32, as3, at3, b3);

    // head: silu(h @ h1W + h1b) -> h32, then h @ h2W + h2b -> out
    wprep_t<<<(256 * 256) / 256, 256>>>(h1W);
    gemm_tc<1><<<G256, 256, GEMM_SMEM>>>(hhi, hlo, whi, wlo, 256, h32, 256, h1b);
    out_kernel<<<NNODES / 8, 256>>>(h32, h2W, h2b, out);
}

// round 5
// speedup vs baseline: 2.0180x; 1.0278x over previous
#include <cuda_runtime.h>
#include <cuda_bf16.h>
#include <cstdint>
#include <math.h>

// ---------------------------------------------------------------------------
// DenoiseGAT on GB300 — Round 5: HMMA GEMMs (3-term bf16 split) + rewritten
// wide-parallel attention kernels (512 thr, float4/bf16x2 vectorized).
// ---------------------------------------------------------------------------

#define NPOLY  2048
#define VPOLY  64
#define NNODES (NPOLY * VPOLY)   // 131072

__device__ __align__(128) __nv_bfloat16 g_hhi[NNODES * 256];
__device__ __align__(128) __nv_bfloat16 g_hlo[NNODES * 256];
__device__ __align__(128) float          g_h32[NNODES * 256];
__device__ __align__(128) float          g_proj[NNODES * 512];
__device__ __align__(128) float          g_temb[NPOLY * 128];
__device__ __align__(128) __nv_bfloat16 g_whi[512 * 256];
__device__ __align__(128) __nv_bfloat16 g_wlo[512 * 256];

__device__ __forceinline__ uint32_t smem_u32(const void* p) {
    uint32_t a;
    asm("{ .reg .u64 t; cvta.to.shared.u64 t, %1; cvt.u32.u64 %0, t; }" : "=r"(a) : "l"(p));
    return a;
}
__device__ __forceinline__ void cp16(uint32_t dst, const void* src) {
    asm volatile("cp.async.cg.shared.global [%0], [%1], 16;" :: "r"(dst), "l"(src) : "memory");
}
#define CP_COMMIT() asm volatile("cp.async.commit_group;" ::: "memory")
#define CP_WAIT0()  asm volatile("cp.async.wait_group 0;" ::: "memory")
#define CP_WAIT1()  asm volatile("cp.async.wait_group 1;" ::: "memory")

__device__ __forceinline__ void ldmx4(uint32_t& r0, uint32_t& r1, uint32_t& r2, uint32_t& r3, uint32_t addr) {
    asm volatile("ldmatrix.sync.aligned.m8n8.x4.shared.b16 {%0,%1,%2,%3}, [%4];"
                 : "=r"(r0), "=r"(r1), "=r"(r2), "=r"(r3) : "r"(addr));
}
__device__ __forceinline__ void mma_bf16(float* d, const uint32_t* a, const uint32_t* b) {
    asm volatile(
        "mma.sync.aligned.m16n8k16.row.col.f32.bf16.bf16.f32 "
        "{%0,%1,%2,%3}, {%4,%5,%6,%7}, {%8,%9}, {%0,%1,%2,%3};"
        : "+f"(d[0]), "+f"(d[1]), "+f"(d[2]), "+f"(d[3])
        : "r"(a[0]), "r"(a[1]), "r"(a[2]), "r"(a[3]), "r"(b[0]), "r"(b[1]));
}

__device__ __forceinline__ float lrelu02(float x) { return x >= 0.f ? x : 0.2f * x; }
__device__ __forceinline__ float eluf(float x)    { return x > 0.f ? x : (expf(x) - 1.f); }
__device__ __forceinline__ float siluf(float x)   { return x / (1.f + expf(-x)); }
__device__ __forceinline__ void split_bf16(float v, __nv_bfloat16& h, __nv_bfloat16& l) {
    h = __float2bfloat16(v);
    l = __float2bfloat16(v - __bfloat162float(h));
}
__device__ __forceinline__ uint32_t pkbf2(__nv_bfloat16 a, __nv_bfloat16 b) {
    __nv_bfloat162 t(a, b);
    return *reinterpret_cast<uint32_t*>(&t);
}

// ---------------------------------------------------------------------------
// HMMA GEMM (unchanged from Round 4): C = A * Bt^T, 3-term bf16 split.
// CTA 128x128, K-tile 32, 256 thr, cp.async 2-stage, 80B smem rows.
// ---------------------------------------------------------------------------
#define TILE_B   10240
#define STAGE_B  (4 * TILE_B)

template <int ACT>
__global__ __launch_bounds__(256) void gemm_tc(
    const __nv_bfloat16* __restrict__ Ahi, const __nv_bfloat16* __restrict__ Alo,
    const __nv_bfloat16* __restrict__ Bhi, const __nv_bfloat16* __restrict__ Blo,
    int K, float* __restrict__ C, int ldc, const float* __restrict__ bias)
{
    extern __shared__ char smem[];
    const uint32_t sb = smem_u32(smem);

    const int tid  = threadIdx.x;
    const int lane = tid & 31;
    const int wid  = tid >> 5;
    const int wm   = wid & 1;
    const int wn   = wid >> 1;
    const int bm   = blockIdx.y * 128;
    const int bn   = blockIdx.x * 128;
    const int KT   = K >> 5;

    const int r0c = (tid) >> 2,        c0 = (tid & 3);
    const int r1c = (tid + 256) >> 2,  c1 = (tid & 3);

    float acc[4][4][4];
#pragma unroll
    for (int i = 0; i < 4; i++)
#pragma unroll
        for (int j = 0; j < 4; j++)
#pragma unroll
            for (int k = 0; k < 4; k++) acc[i][j][k] = 0.f;

#define ISSUE_STAGE(kt, s)                                                            \
    do {                                                                              \
        int kof = (kt) * 32;                                                          \
        uint32_t sba = sb + (s) * STAGE_B;                                            \
        cp16(sba + r0c * 80 + c0 * 16,              Ahi + (size_t)(bm + r0c) * K + kof + c0 * 8); \
        cp16(sba + r1c * 80 + c1 * 16,              Ahi + (size_t)(bm + r1c) * K + kof + c1 * 8); \
        cp16(sba + TILE_B + r0c * 80 + c0 * 16,     Alo + (size_t)(bm + r0c) * K + kof + c0 * 8); \
        cp16(sba + TILE_B + r1c * 80 + c1 * 16,     Alo + (size_t)(bm + r1c) * K + kof + c1 * 8); \
        cp16(sba + 2 * TILE_B + r0c * 80 + c0 * 16, Bhi + (size_t)(bn + r0c) * K + kof + c0 * 8); \
        cp16(sba + 2 * TILE_B + r1c * 80 + c1 * 16, Bhi + (size_t)(bn + r1c) * K + kof + c1 * 8); \
        cp16(sba + 3 * TILE_B + r0c * 80 + c0 * 16, Blo + (size_t)(bn + r0c) * K + kof + c0 * 8); \
        cp16(sba + 3 * TILE_B + r1c * 80 + c1 * 16, Blo + (size_t)(bn + r1c) * K + kof + c1 * 8); \
    } while (0)

    ISSUE_STAGE(0, 0);
    CP_COMMIT();

    const int aRow  = wm * 64 + (lane & 15);
    const int aHalf = lane >> 4;
    const int bRow  = wn * 32 + (lane & 7) + ((lane >> 4) << 3);
    const int bHalf = (lane >> 3) & 1;

    for (int kt = 0; kt < KT; kt++) {
        if (kt + 1 < KT) {
            ISSUE_STAGE(kt + 1, (kt + 1) & 1);
            CP_COMMIT();
            CP_WAIT1();
        } else {
            CP_WAIT0();
        }
        __syncthreads();

        const uint32_t sba = sb + (kt & 1) * STAGE_B;
#pragma unroll
        for (int ks = 0; ks < 2; ks++) {
            uint32_t Ah[4][4], Al[4][4], Bh[4][2], Bl[4][2];
#pragma unroll
            for (int mf = 0; mf < 4; mf++) {
                uint32_t ad = sba + (aRow + mf * 16) * 80 + (2 * ks + aHalf) * 16;
                ldmx4(Ah[mf][0], Ah[mf][1], Ah[mf][2], Ah[mf][3], ad);
                ldmx4(Al[mf][0], Al[mf][1], Al[mf][2], Al[mf][3], ad + TILE_B);
            }
#pragma unroll
            for (int nfp = 0; nfp < 2; nfp++) {
                uint32_t bd = sba + 2 * TILE_B + (bRow + nfp * 16) * 80 + (2 * ks + bHalf) * 16;
                uint32_t q0, q1, q2, q3;
                ldmx4(q0, q1, q2, q3, bd);
                Bh[nfp * 2][0] = q0; Bh[nfp * 2][1] = q1;
                Bh[nfp * 2 + 1][0] = q2; Bh[nfp * 2 + 1][1] = q3;
                ldmx4(q0, q1, q2, q3, bd + TILE_B);
                Bl[nfp * 2][0] = q0; Bl[nfp * 2][1] = q1;
                Bl[nfp * 2 + 1][0] = q2; Bl[nfp * 2 + 1][1] = q3;
            }
#pragma unroll
            for (int mf = 0; mf < 4; mf++)
#pragma unroll
                for (int nf = 0; nf < 4; nf++) {
                    mma_bf16(acc[mf][nf], Ah[mf], Bh[nf]);
                    mma_bf16(acc[mf][nf], Ah[mf], Bl[nf]);
                    mma_bf16(acc[mf][nf], Al[mf], Bh[nf]);
                }
        }
        __syncthreads();
    }

#pragma unroll
    for (int mf = 0; mf < 4; mf++) {
        int m0 = bm + wm * 64 + mf * 16 + (lane >> 2);
#pragma unroll
        for (int nf = 0; nf < 4; nf++) {
            int n0 = bn + wn * 32 + nf * 8 + (lane & 3) * 2;
            float v0 = acc[mf][nf][0], v1 = acc[mf][nf][1];
            float v2 = acc[mf][nf][2], v3 = acc[mf][nf][3];
            if (ACT == 1) {
                float bb0 = bias[n0], bb1 = bias[n0 + 1];
                v0 = siluf(v0 + bb0); v1 = siluf(v1 + bb1);
                v2 = siluf(v2 + bb0); v3 = siluf(v3 + bb1);
            }
            *(float2*)&C[(size_t)m0 * ldc + n0]       = make_float2(v0, v1);
            *(float2*)&C[(size_t)(m0 + 8) * ldc + n0] = make_float2(v2, v3);
        }
    }
}

// ---------------------------------------------------------------------------
// temb: SinusoidalPosEmb(128) -> Linear(128,128) -> SiLU.  grid=2048, 128 thr
// ---------------------------------------------------------------------------
__global__ void temb_kernel(const int* __restrict__ t, const float* __restrict__ tW,
                            const float* __restrict__ tb, float* __restrict__ temb)
{
    __shared__ float pe[128];
    int b = blockIdx.x, c = threadIdx.x;
    float tv = (float)t[b];
    if (c < 64) {
        float fr = expf(-logf(10000.0f) * (float)c * (1.0f / 63.0f));
        float te = tv * fr;
        pe[c]      = sinf(te);
        pe[c + 64] = cosf(te);
    }
    __syncthreads();
    float acc = tb[c];
#pragma unroll 8
    for (int k = 0; k < 128; k++) acc += pe[k] * tW[k * 128 + c];
    temb[b * 128 + c] = siluf(acc);
}

// ---------------------------------------------------------------------------
// assemble h0 (N x 160 bf16 hi/lo, cols 134..159 zero).  grid=N, 160 threads
// ---------------------------------------------------------------------------
__global__ void assemble_kernel(const float* __restrict__ x, const float* __restrict__ temb)
{
    int n = blockIdx.x, c = threadIdx.x;
    int b = n >> 6, v = n & 63;
    float val = 0.f;
    if (c < 2) {
        val = x[b * 128 + v * 2 + c];
    } else if (c < 6) {
        float ph  = (float)v * (6.283185307179586f / 64.f);
        float arg = (c < 4) ? ph : 2.f * ph;
        val = ((c & 1) == 0) ? sinf(arg) : cosf(arg);
    } else if (c < 134) {
        val = temb[b * 128 + c - 6];
    }
    __nv_bfloat16 h, l;
    split_bf16(val, h, l);
    g_hhi[(size_t)n * 160 + c] = h;
    g_hlo[(size_t)n * 160 + c] = l;
}

// ---------------------------------------------------------------------------
// Weight prep
// ---------------------------------------------------------------------------
__global__ void wprep_cat(const float* __restrict__ W, const float* __restrict__ skip,
                          int K, int Kpad)
{
    int idx = blockIdx.x * 256 + threadIdx.x;
    if (idx >= 512 * Kpad) return;
    int n = idx / Kpad, k = idx % Kpad;
    float v = 0.f;
    if (k < K) v = (n < 256) ? W[k * 256 + n] : skip[k * 256 + (n - 256)];
    __nv_bfloat16 h, l;
    split_bf16(v, h, l);
    g_whi[idx] = h; g_wlo[idx] = l;
}
__global__ void wprep_t(const float* __restrict__ W)
{
    int idx = blockIdx.x * 256 + threadIdx.x;
    int n = idx >> 8, k = idx & 255;
    float v = W[k * 256 + n];
    __nv_bfloat16 h, l;
    split_bf16(v, h, l);
    g_whi[idx] = h; g_wlo[idx] = l;
}

// ---------------------------------------------------------------------------
// att4 v2: NH=4, FOUT=64, 512 threads, vectorized aggregation.
// ---------------------------------------------------------------------------
template <int WRITE32>
__global__ __launch_bounds__(512) void att4_kernel(
    const float* __restrict__ proj,
    const float* __restrict__ asrc, const float* __restrict__ atgt,
    const float* __restrict__ bias)
{
    extern __shared__ float sm[];
    float* sp  = sm;            // 64*256
    float* sS  = sm + 16384;    // 256
    float* sT  = sS + 256;
    float* aP  = sT + 256;
    float* aN  = aP + 256;
    float* aSf = aN + 256;
    float* sa  = aSf + 256;
    float* sg  = sa + 256;

    const int tid = threadIdx.x;
    const int nb  = blockIdx.x * 64;

    for (int i = tid; i < 4096; i += 512) {
        int j = i >> 6, c = (i & 63) << 2;
        *(float4*)&sp[j * 256 + c] = *(const float4*)&proj[(size_t)(nb + j) * 512 + c];
    }
    if (tid < 256) { sa[tid] = asrc[tid]; sg[tid] = atgt[tid]; }
    __syncthreads();

    {   // scores: pair of threads per (j,h); 32 elems each + shfl reduce
        int pair = tid >> 1, half = tid & 1;
        int j = pair >> 2, h = pair & 3;
        const float* row = sp + j * 256 + h * 64 + half * 32;
        const float* wa  = sa + h * 64 + half * 32;
        const float* wg  = sg + h * 64 + half * 32;
        float ss = 0.f, st = 0.f;
#pragma unroll
        for (int f = 0; f < 32; f++) {
            float p = row[f];
            ss += p * wa[f];
            st += p * wg[f];
        }
        ss += __shfl_xor_sync(0xffffffffu, ss, 1);
        st += __shfl_xor_sync(0xffffffffu, st, 1);
        if (!half) { sS[pair] = ss; sT[pair] = st; }
    }
    __syncthreads();

    if (tid < 256) {   // softmax over {prev, next, self}
        int j = tid >> 2, h = tid & 3;
        int jp = (j + 63) & 63, jn = (j + 1) & 63;
        float tg = sT[j * 4 + h];
        float ep = lrelu02(sS[jp * 4 + h] + tg);
        float en = lrelu02(sS[jn * 4 + h] + tg);
        float es = lrelu02(sS[j * 4 + h]  + tg);
        float m  = fmaxf(ep, fmaxf(en, es));
        ep = expf(ep - m); en = expf(en - m); es = expf(es - m);
        float inv = 1.f / (ep + en + es + 1e-16f);
        aP[j * 4 + h]  = ep * inv;
        aN[j * 4 + h]  = en * inv;
        aSf[j * 4 + h] = es * inv;
    }
    __syncthreads();

    {   // aggregation: thread -> (col quad, j octet)
        const int c4 = (tid & 63) << 2;
        const int j0 = (tid >> 6) << 3;
        const int h  = c4 >> 6;
        const float4 bv = *(const float4*)&bias[c4];
#pragma unroll
        for (int jj = 0; jj < 8; jj++) {
            int j = j0 + jj, jp = (j + 63) & 63, jn = (j + 1) & 63;
            float ap = aP[j * 4 + h], an = aN[j * 4 + h], af = aSf[j * 4 + h];
            float4 pp = *(const float4*)&sp[jp * 256 + c4];
            float4 pn = *(const float4*)&sp[jn * 256 + c4];
            float4 ps = *(const float4*)&sp[j  * 256 + c4];
            float4 sk = *(const float4*)&proj[(size_t)(nb + j) * 512 + 256 + c4];
            float v0 = eluf(ap * pp.x + an * pn.x + af * ps.x + sk.x + bv.x);
            float v1 = eluf(ap * pp.y + an * pn.y + af * ps.y + sk.y + bv.y);
            float v2 = eluf(ap * pp.z + an * pn.z + af * ps.z + sk.z + bv.z);
            float v3 = eluf(ap * pp.w + an * pn.w + af * ps.w + sk.w + bv.w);
            __nv_bfloat16 h0, l0, h1, l1, h2, l2, h3, l3;
            split_bf16(v0, h0, l0); split_bf16(v1, h1, l1);
            split_bf16(v2, h2, l2); split_bf16(v3, h3, l3);
            size_t o = (size_t)(nb + j) * 256 + c4;
            *(uint2*)&g_hhi[o] = make_uint2(pkbf2(h0, h1), pkbf2(h2, h3));
            *(uint2*)&g_hlo[o] = make_uint2(pkbf2(l0, l1), pkbf2(l2, l3));
            if (WRITE32) *(float4*)&g_h32[o] = make_float4(v0, v1, v2, v3);
        }
    }
}

// ---------------------------------------------------------------------------
// att1 v2: NH=1, FOUT=256, identity residual, 512 threads.
// ---------------------------------------------------------------------------
__global__ __launch_bounds__(512) void att1_kernel(
    const float* __restrict__ proj,      // N x 256
    const float* __restrict__ hprev,     // N x 256 (fp32)
    const float* __restrict__ asrc, const float* __restrict__ atgt,
    const float* __restrict__ bias)
{
    extern __shared__ float sm[];
    float* sp   = sm;              // 64*256
    float* redS = sm + 16384;      // 512
    float* redT = redS + 512;      // 512
    float* sS   = redT + 512;      // 64
    float* sT   = sS + 64;
    float* aP   = sT + 64;
    float* aN   = aP + 64;
    float* aSf  = aN + 64;
    float* sa   = aSf + 64;        // 256
    float* sg   = sa + 256;        // 256

    const int tid = threadIdx.x;
    const int nb  = blockIdx.x * 64;

    for (int i = tid; i < 4096; i += 512) {
        int j = i >> 6, c = (i & 63) << 2;
        *(float4*)&sp[j * 256 + c] = *(const float4*)&proj[(size_t)(nb + j) * 256 + c];
    }
    if (tid < 256) { sa[tid] = asrc[tid]; sg[tid] = atgt[tid]; }
    __syncthreads();

    {   // partial dots: j = tid&63, segment r = tid>>6 (32 elems)
        int j = tid & 63, r = tid >> 6;
        const float* row = sp + j * 256 + r * 32;
        const float* wa  = sa + r * 32;
        const float* wg  = sg + r * 32;
        float ss = 0.f, st = 0.f;
#pragma unroll
        for (int f = 0; f < 32; f++) {
            float p = row[f];
            ss += p * wa[f];
            st += p * wg[f];
        }
        redS[r * 64 + j] = ss;
        redT[r * 64 + j] = st;
    }
    __syncthreads();
    if (tid < 64) {
        float ss = 0.f, st = 0.f;
#pragma unroll
        for (int r = 0; r < 8; r++) { ss += redS[r * 64 + tid]; st += redT[r * 64 + tid]; }
        sS[tid] = ss; sT[tid] = st;
    }
    __syncthreads();
    if (tid < 64) {
        int j = tid, jp = (j + 63) & 63, jn = (j + 1) & 63;
        float tg = sT[j];
        float ep = lrelu02(sS[jp] + tg);
        float en = lrelu02(sS[jn] + tg);
        float es = lrelu02(sS[j]  + tg);
        float m  = fmaxf(ep, fmaxf(en, es));
        ep = expf(ep - m); en = expf(en - m); es = expf(es - m);
        float inv = 1.f / (ep + en + es + 1e-16f);
        aP[j] = ep * inv; aN[j] = en * inv; aSf[j] = es * inv;
    }
    __syncthreads();

    {
        const int c4 = (tid & 63) << 2;
        const int j0 = (tid >> 6) << 3;
        const float4 bv = *(const float4*)&bias[c4];
#pragma unroll
        for (int jj = 0; jj < 8; jj++) {
            int j = j0 + jj, jp = (j + 63) & 63, jn = (j + 1) & 63;
            float ap = aP[j], an = aN[j], af = aSf[j];
            float4 pp = *(const float4*)&sp[jp * 256 + c4];
            float4 pn = *(const float4*)&sp[jn * 256 + c4];
            float4 ps = *(const float4*)&sp[j  * 256 + c4];
            float4 hp = *(const float4*)&hprev[(size_t)(nb + j) * 256 + c4];
            float v0 = ap * pp.x + an * pn.x + af * ps.x + hp.x + bv.x;
            float v1 = ap * pp.y + an * pn.y + af * ps.y + hp.y + bv.y;
            float v2 = ap * pp.z + an * pn.z + af * ps.z + hp.z + bv.z;
            float v3 = ap * pp.w + an * pn.w + af * ps.w + hp.w + bv.w;
            __nv_bfloat16 h0, l0, h1, l1, h2, l2, h3, l3;
            split_bf16(v0, h0, l0); split_bf16(v1, h1, l1);
            split_bf16(v2, h2, l2); split_bf16(v3, h3, l3);
            size_t o = (size_t)(nb + j) * 256 + c4;
            *(uint2*)&g_hhi[o] = make_uint2(pkbf2(h0, h1), pkbf2(h2, h3));
            *(uint2*)&g_hlo[o] = make_uint2(pkbf2(l0, l1), pkbf2(l2, l3));
        }
    }
}

// ---------------------------------------------------------------------------
// Final projection: out[n, 0:2] = h[n, :] @ h2W + h2b. One warp per node.
// ---------------------------------------------------------------------------
__global__ __launch_bounds__(256) void out_kernel(
    const float* __restrict__ h, const float* __restrict__ w,
    const float* __restrict__ b2, float* __restrict__ out)
{
    int gw   = blockIdx.x * 8 + (threadIdx.x >> 5);
    int lane = threadIdx.x & 31;
    const float* hr = h + (size_t)gw * 256;
    float s0 = 0.f, s1 = 0.f;
#pragma unroll
    for (int k = lane; k < 256; k += 32) {
        float hv = hr[k];
        s0 += hv * w[k * 2];
        s1 += hv * w[k * 2 + 1];
    }
#pragma unroll
    for (int off = 16; off; off >>= 1) {
        s0 += __shfl_down_sync(0xffffffffu, s0, off);
        s1 += __shfl_down_sync(0xffffffffu, s1, off);
    }
    if (lane == 0) {
        out[(size_t)gw * 2]     = s0 + b2[0];
        out[(size_t)gw * 2 + 1] = s1 + b2[1];
    }
}

// ---------------------------------------------------------------------------
extern "C" void kernel_launch(void* const* d_in, const int* in_sizes, int n_in,
                              void* d_out, int out_size)
{
    const float* x   = (const float*)d_in[0];
    const int*   t   = (const int*)  d_in[1];
    const float* tW  = (const float*)d_in[2];
    const float* tb  = (const float*)d_in[3];
    const float* W0  = (const float*)d_in[4];
    const float* as0 = (const float*)d_in[5];
    const float* at0 = (const float*)d_in[6];
    const float* b0  = (const float*)d_in[7];
    const float* W1  = (const float*)d_in[8];
    const float* as1 = (const float*)d_in[9];
    const float* at1 = (const float*)d_in[10];
    const float* b1  = (const float*)d_in[11];
    const float* W2  = (const float*)d_in[12];
    const float* as2 = (const float*)d_in[13];
    const float* at2 = (const float*)d_in[14];
    const float* b2_ = (const float*)d_in[15];
    const float* W3  = (const float*)d_in[16];
    const float* as3 = (const float*)d_in[17];
    const float* at3 = (const float*)d_in[18];
    const float* b3  = (const float*)d_in[19];
    const float* sk0 = (const float*)d_in[20];
    const float* sk1 = (const float*)d_in[21];
    const float* sk2 = (const float*)d_in[22];
    const float* h1W = (const float*)d_in[23];
    const float* h1b = (const float*)d_in[24];
    const float* h2W = (const float*)d_in[25];
    const float* h2b = (const float*)d_in[26];
    float* out = (float*)d_out;

    __nv_bfloat16 *hhi, *hlo, *whi, *wlo;
    float *h32, *proj, *temb;
    cudaGetSymbolAddress((void**)&hhi,  g_hhi);
    cudaGetSymbolAddress((void**)&hlo,  g_hlo);
    cudaGetSymbolAddress((void**)&h32,  g_h32);
    cudaGetSymbolAddress((void**)&proj, g_proj);
    cudaGetSymbolAddress((void**)&temb, g_temb);
    cudaGetSymbolAddress((void**)&whi,  g_whi);
    cudaGetSymbolAddress((void**)&wlo,  g_wlo);

    const int GEMM_SMEM = 2 * STAGE_B;   // 81920
    cudaFuncSetAttribute(gemm_tc<0>, cudaFuncAttributeMaxDynamicSharedMemorySize, GEMM_SMEM);
    cudaFuncSetAttribute(gemm_tc<1>, cudaFuncAttributeMaxDynamicSharedMemorySize, GEMM_SMEM);

    const int ATT4_SMEM = (16384 + 7 * 256) * 4;                  // 72704
    const int ATT1_SMEM = (16384 + 2 * 512 + 5 * 64 + 2 * 256) * 4; // 72768... (sized below)
    cudaFuncSetAttribute(att4_kernel<0>, cudaFuncAttributeMaxDynamicSharedMemorySize, ATT4_SMEM);
    cudaFuncSetAttribute(att4_kernel<1>, cudaFuncAttributeMaxDynamicSharedMemorySize, ATT4_SMEM);
    cudaFuncSetAttribute(att1_kernel,    cudaFuncAttributeMaxDynamicSharedMemorySize, ATT1_SMEM);

    const dim3 G512(4, NNODES / 128), G256(2, NNODES / 128);

    temb_kernel<<<NPOLY, 128>>>(t, tW, tb, temb);
    assemble_kernel<<<NNODES, 160>>>(x, temb);

    // layer 0: K=134 padded to 160
    wprep_cat<<<(512 * 160 + 255) / 256, 256>>>(W0, sk0, 134, 160);
    gemm_tc<0><<<G512, 256, GEMM_SMEM>>>(hhi, hlo, whi, wlo, 160, proj, 512, nullptr);
    att4_kernel<0><<<NPOLY, 512, ATT4_SMEM>>>(proj, as0, at0, b0);

    // layer 1
    wprep_cat<<<(512 * 256 + 255) / 256, 256>>>(W1, sk1, 256, 256);
    gemm_tc<0><<<G512, 256, GEMM_SMEM>>>(hhi, hlo, whi, wlo, 256, proj, 512, nullptr);
    att4_kernel<0><<<NPOLY, 512, ATT4_SMEM>>>(proj, as1, at1, b1);

    // layer 2 (fp32 output needed for layer-3 residual)
    wprep_cat<<<(512 * 256 + 255) / 256, 256>>>(W2, sk2, 256, 256);
    gemm_tc<0><<<G512, 256, GEMM_SMEM>>>(hhi, hlo, whi, wlo, 256, proj, 512, nullptr);
    att4_kernel<1><<<NPOLY, 512, ATT4_SMEM>>>(proj, as2, at2, b2_);

    // layer 3 (NH=1, identity residual, no act)
    wprep_t<<<(256 * 256) / 256, 256>>>(W3);
    gemm_tc<0><<<G256, 256, GEMM_SMEM>>>(hhi, hlo, whi, wlo, 256, proj, 256, nullptr);
    att1_kernel<<<NPOLY, 512, ATT1_SMEM>>>(proj, h32, as3, at3, b3);

    // head: silu(h @ h1W + h1b) -> h32, then h @ h2W + h2b -> out
    wprep_t<<<(256 * 256) / 256, 256>>>(h1W);
    gemm_tc<1><<<G256, 256, GEMM_SMEM>>>(hhi, hlo, whi, wlo, 256, h32, 256, h1b);
    out_kernel<<<NNODES / 8, 256>>>(h32, h2W, h2b, out);
}